// round 9
// baseline (speedup 1.0000x reference)
#include <cuda_runtime.h>
#include <cuda_fp16.h>
#include <cstdint>

// ============================================================================
// X[16,4096,256] -> proj(256->128)+bp -> relu(W1+b1) -> W2+b2 = Y
// out[b,n,:] = sum_m Y[b,m,:] - Y[b,n,:]
// mma.sync.m16n8k16 fp16/f32. 512 CTAs x 512 thr (16 warps, 4/SMSP):
// warp w -> rows (w>>1)*16..+16, n-half (w&1)*64..+64. acc = 32 regs/warp.
// Weights streamed in 16KB chunks (double-buffered cp.async); X fp16 in SMEM,
// H1/H2 reuse the X buffer. A-frags via one ldmatrix.x4 per k-step.
// Column sums fused into the final epilogue -> g_part[tile][128].
// ============================================================================

__device__ __align__(16) uint32_t g_wpack[8 * 4096];  // 8 chunks x 16KB fp16 packed
__device__ float g_part[512 * 128];

// ---------------- helpers ----------------
__device__ __forceinline__ uint32_t smem_u32(const void* p) {
    uint32_t a;
    asm("{ .reg .u64 t; cvta.to.shared.u64 t, %1; cvt.u32.u64 %0, t; }" : "=r"(a) : "l"(p));
    return a;
}
__device__ __forceinline__ void lds64f(uint32_t a, float& x, float& y) {
    asm volatile("ld.shared.v2.f32 {%0,%1}, [%2];" : "=f"(x), "=f"(y) : "r"(a));
}
__device__ __forceinline__ void lds128u(uint32_t a, uint32_t& x, uint32_t& y, uint32_t& z, uint32_t& w) {
    asm volatile("ld.shared.v4.b32 {%0,%1,%2,%3}, [%4];" : "=r"(x), "=r"(y), "=r"(z), "=r"(w) : "r"(a));
}
__device__ __forceinline__ void sts32u(uint32_t a, uint32_t v) {
    asm volatile("st.shared.b32 [%0], %1;" :: "r"(a), "r"(v));
}
__device__ __forceinline__ void sts128u(uint32_t a, uint32_t x, uint32_t y, uint32_t z, uint32_t w) {
    asm volatile("st.shared.v4.b32 [%0], {%1,%2,%3,%4};" :: "r"(a), "r"(x), "r"(y), "r"(z), "r"(w));
}
__device__ __forceinline__ uint32_t packh2(float lo, float hi) {
    uint32_t u;
    asm("cvt.rn.f16x2.f32 %0, %1, %2;" : "=r"(u) : "f"(hi), "f"(lo));
    return u;
}
__device__ __forceinline__ void ldmA4(uint32_t a, uint32_t* r) {
    asm volatile("ldmatrix.sync.aligned.m8n8.x4.shared.b16 {%0,%1,%2,%3}, [%4];"
        : "=r"(r[0]), "=r"(r[1]), "=r"(r[2]), "=r"(r[3]) : "r"(a));
}
__device__ __forceinline__ void mma16(float* d,
                                      uint32_t a0, uint32_t a1, uint32_t a2, uint32_t a3,
                                      uint32_t b0, uint32_t b1) {
    asm volatile(
        "mma.sync.aligned.m16n8k16.row.col.f32.f16.f16.f32 "
        "{%0,%1,%2,%3}, {%4,%5,%6,%7}, {%8,%9}, {%0,%1,%2,%3};"
        : "+f"(d[0]), "+f"(d[1]), "+f"(d[2]), "+f"(d[3])
        : "r"(a0), "r"(a1), "r"(a2), "r"(a3), "r"(b0), "r"(b1));
}
#define CP16(dst, src)  asm volatile("cp.async.cg.shared.global [%0], [%1], 16;" :: "r"(dst), "l"(src))
#define CP_COMMIT()     asm volatile("cp.async.commit_group;" ::: "memory")
#define CP_WAIT(n)      asm volatile("cp.async.wait_group %0;" :: "n"(n) : "memory")

// ============================================================================
// prep: pack weights (fp16) into lane-ordered quad layout (proven R4-R8).
// chunk c (0..7) = 16KB K-slice of 64 rows x 128 cols (0-3:Wp, 4-5:W1, 6-7:W2).
// uint32 idx within chunk: ((ks*8+bp)*32 + lane)*4 + q, where
//   k_local = ks*16 + (q&1)*8 + (lane&3)*2 ; n = bp*16 + (q>>1)*8 + (lane>>2)
// ============================================================================
__global__ void prep_kernel(const float* __restrict__ Wp,
                            const float* __restrict__ W1,
                            const float* __restrict__ W2) {
    int i = blockIdx.x * 256 + threadIdx.x;          // 32768 total
    int chunk = i >> 12;
    int within = i & 4095;
    int q = within & 3, ln = (within >> 2) & 31, bpks = within >> 7;
    int bpi = bpks & 7, ks = bpks >> 3;
    int kl = ks * 16 + (q & 1) * 8 + (ln & 3) * 2;
    int n = bpi * 16 + (q >> 1) * 8 + (ln >> 2);
    const float* W;
    int krow;
    if (chunk < 4)      { W = Wp; krow = chunk * 64 + kl; }
    else if (chunk < 6) { W = W1; krow = (chunk - 4) * 64 + kl; }
    else                { W = W2; krow = (chunk - 6) * 64 + kl; }
    float w0 = W[(size_t)krow * 128 + n];
    float w1 = W[(size_t)(krow + 1) * 128 + n];
    g_wpack[i] = packh2(w0, w1);
}

// ============================================================================
// fused kernel — ~104KB SMEM, 512 threads (16 warps).
// SMEM: X/H region (fp16, stride 528 -> 272) | W dbl buf 2x16KB | bias | red
// ============================================================================
#define SM_X    0
#define SM_W0   67584                 // 128*528
#define SM_W1B  83968
#define SM_BIAS 100352                // bp[128], b1[128], b2[128] (f32)
#define SM_RED  101888                // 8*128 floats
#define SMEM_SZ 105984

// one 16KB chunk = 4 k-steps of 16. a_lane = ldmatrix lane base, astr = row
// stride, a_off = byte offset of this chunk's first k-block within A rows.
__device__ __forceinline__ void gemm_chunk(uint32_t a_lane, uint32_t a_off,
                                           uint32_t wb, int nh, int l, float acc[8][4]) {
    #pragma unroll
    for (int ks = 0; ks < 4; ++ks) {
        uint32_t A[4];
        ldmA4(a_lane + a_off + (uint32_t)ks * 32, A);
        uint32_t bb = wb + (uint32_t)ks * 4096 + (uint32_t)(nh * 4) * 512 + (uint32_t)l * 16;
        #pragma unroll
        for (int bpi = 0; bpi < 4; ++bpi) {
            uint32_t q0, q1, q2, q3;
            lds128u(bb + (uint32_t)bpi * 512, q0, q1, q2, q3);
            mma16(acc[2 * bpi],     A[0], A[1], A[2], A[3], q0, q1);
            mma16(acc[2 * bpi + 1], A[0], A[1], A[2], A[3], q2, q3);
        }
    }
}

__global__ void __launch_bounds__(512, 1) fused_kernel(
    const float* __restrict__ X,
    const float* __restrict__ bp,
    const float* __restrict__ b1,
    const float* __restrict__ b2,
    float* __restrict__ out)
{
    extern __shared__ char smem[];
    const uint32_t sb = smem_u32(smem);
    const int tid = threadIdx.x;
    const int l = tid & 31;
    const int w = tid >> 5;
    const int wrow = (w >> 1) * 16;        // row group (16 rows per warp)
    const int nh = w & 1;                  // n-half
    const int t = blockIdx.x;

    // prefetch weight chunks 0,1 (two cp.async groups)
    {
        const uint4* ws = (const uint4*)g_wpack;
        for (int i = tid; i < 1024; i += 512) CP16(sb + SM_W0 + i * 16, ws + i);
        CP_COMMIT();
        for (int i = tid; i < 1024; i += 512) CP16(sb + SM_W1B + i * 16, ws + 1024 + i);
        CP_COMMIT();
    }
    if (tid < 128) {
        ((float*)(smem + SM_BIAS))[tid]       = bp[tid];
        ((float*)(smem + SM_BIAS))[128 + tid] = b1[tid];
        ((float*)(smem + SM_BIAS))[256 + tid] = b2[tid];
    }

    // X tile -> fp16 smem (row = tid>>2, 64-col seg = tid&3), stride 528
    {
        const int row = tid >> 2, seg = tid & 3;
        const float4* xp = (const float4*)(X + ((size_t)t * 128 + row) * 256 + seg * 64);
        uint32_t sa = sb + SM_X + (uint32_t)row * 528 + (uint32_t)seg * 128;
        #pragma unroll
        for (int j = 0; j < 8; ++j) {
            float4 v0 = xp[2 * j], v1 = xp[2 * j + 1];
            sts128u(sa + (uint32_t)j * 16,
                    packh2(v0.x, v0.y), packh2(v0.z, v0.w),
                    packh2(v1.x, v1.y), packh2(v1.z, v1.w));
        }
    }
    __syncthreads();   // X visible to all warps (weight waits happen per-chunk)

    float acc[8][4];
    #pragma unroll
    for (int nb = 0; nb < 8; ++nb)
        #pragma unroll
        for (int k = 0; k < 4; ++k) acc[nb][k] = 0.f;

    const uint32_t lm_row = (uint32_t)(l & 15);
    const uint32_t lm_hi  = (uint32_t)(l >> 4) * 16;
    const uint32_t aX = sb + SM_X + ((uint32_t)wrow + lm_row) * 528 + lm_hi;   // stride 528
    const uint32_t aH = sb + SM_X + ((uint32_t)wrow + lm_row) * 272 + lm_hi;   // stride 272

    for (int ch = 0; ch < 8; ++ch) {
        if (ch < 7) { CP_WAIT(1); } else { CP_WAIT(0); }
        __syncthreads();   // chunk ch ready for ALL threads; prev chunk reads done

        const uint32_t wb = sb + ((ch & 1) ? SM_W1B : SM_W0);
        if (ch < 4)        gemm_chunk(aX, (uint32_t)ch * 128,       wb, nh, l, acc);
        else if (ch < 6)   gemm_chunk(aH, (uint32_t)(ch - 4) * 128, wb, nh, l, acc);
        else               gemm_chunk(aH, (uint32_t)(ch - 6) * 128, wb, nh, l, acc);

        if (ch == 3 || ch == 5) {
            __syncthreads();   // all reads of X/H1 done before overwrite
            const uint32_t bo = sb + SM_BIAS + (ch == 3 ? 0 : 512) + (uint32_t)nh * 256;
            const bool dorelu = (ch == 5);
            #pragma unroll
            for (int nb = 0; nb < 8; ++nb) {
                float bx, by;
                lds64f(bo + (uint32_t)(nb * 8 + (l & 3) * 2) * 4, bx, by);
                float v0 = acc[nb][0] + bx, v1 = acc[nb][1] + by;
                float v2 = acc[nb][2] + bx, v3 = acc[nb][3] + by;
                if (dorelu) {
                    v0 = fmaxf(v0, 0.f); v1 = fmaxf(v1, 0.f);
                    v2 = fmaxf(v2, 0.f); v3 = fmaxf(v3, 0.f);
                }
                uint32_t sa = sb + SM_X + (uint32_t)(wrow + (l >> 2)) * 272
                                        + (uint32_t)(nh * 64 + nb * 8 + (l & 3) * 2) * 2;
                sts32u(sa, packh2(v0, v1));
                sts32u(sa + 8 * 272, packh2(v2, v3));
                acc[nb][0] = 0.f; acc[nb][1] = 0.f;
                acc[nb][2] = 0.f; acc[nb][3] = 0.f;
            }
        } else if (ch == 7) {
            // final epilogue: Y -> gmem, fused per-tile column sums
            const size_t rb = (size_t)t * 128 + wrow + (l >> 2);
            float cs[8][2];
            #pragma unroll
            for (int nb = 0; nb < 8; ++nb) { cs[nb][0] = 0.f; cs[nb][1] = 0.f; }
            #pragma unroll
            for (int nb = 0; nb < 8; ++nb) {
                float bx, by;
                lds64f(sb + SM_BIAS + 1024 + (uint32_t)(nh * 64 + nb * 8 + (l & 3) * 2) * 4, bx, by);
                float v0 = acc[nb][0] + bx, v1 = acc[nb][1] + by;
                float v2 = acc[nb][2] + bx, v3 = acc[nb][3] + by;
                size_t r0 = rb * 128 + nh * 64 + nb * 8 + (l & 3) * 2;
                *(float2*)(out + r0)           = make_float2(v0, v1);
                *(float2*)(out + r0 + 8 * 128) = make_float2(v2, v3);
                cs[nb][0] += v0 + v2;
                cs[nb][1] += v1 + v3;
            }
            #pragma unroll
            for (int nb = 0; nb < 8; ++nb) {
                #pragma unroll
                for (int j = 0; j < 2; ++j) {
                    float s = cs[nb][j];
                    s += __shfl_down_sync(0xFFFFFFFFu, s, 16);
                    s += __shfl_down_sync(0xFFFFFFFFu, s, 8);
                    s += __shfl_down_sync(0xFFFFFFFFu, s, 4);
                    if (l < 4)
                        ((float*)(smem + SM_RED))[(w >> 1) * 128 + nh * 64 + nb * 8 + l * 2 + j] = s;
                }
            }
        }

        __syncthreads();   // protects weight-buffer reuse + H transitions

        if (ch + 2 < 8) {  // prefetch weight chunk ch+2 into buffer (ch&1)
            const uint4* ws = (const uint4*)(g_wpack + (ch + 2) * 4096);
            uint32_t bdst = sb + ((ch & 1) ? SM_W1B : SM_W0);
            for (int i = tid; i < 1024; i += 512) CP16(bdst + i * 16, ws + i);
            CP_COMMIT();
        }
    }

    // fold 8 row-groups -> g_part[t][128]
    if (tid < 128) {
        const float* R = (const float*)(smem + SM_RED);
        float s = 0.f;
        #pragma unroll
        for (int g = 0; g < 8; ++g) s += R[g * 128 + tid];
        g_part[(size_t)t * 128 + tid] = s;
    }
}

// ---------------- out = S - Y (in place, float4) ----------------
__global__ void subtract_kernel(float* __restrict__ out) {
    __shared__ float4 S4[32];
    int b = blockIdx.x, nc = blockIdx.y, tid = threadIdx.x;
    if (tid < 128) {
        float s = 0.f;
        const float* gp = g_part + (size_t)b * 32 * 128 + tid;
        #pragma unroll
        for (int c = 0; c < 32; ++c) s += gp[c * 128];
        ((float*)S4)[tid] = s;
    }
    __syncthreads();
    float4* p = (float4*)(out + ((size_t)b * 4096 + (size_t)nc * 128) * 128);
    for (int i = tid; i < 4096; i += 256) {
        float4 s = S4[i & 31];
        float4 v = p[i];
        p[i] = make_float4(s.x - v.x, s.y - v.y, s.z - v.z, s.w - v.w);
    }
}

// ---------------- launch ----------------
extern "C" void kernel_launch(void* const* d_in, const int* in_sizes, int n_in,
                              void* d_out, int out_size) {
    const float* X  = (const float*)d_in[0];
    const float* Wp = (const float*)d_in[1];
    const float* bp = (const float*)d_in[2];
    const float* W1 = (const float*)d_in[3];
    const float* b1 = (const float*)d_in[4];
    const float* W2 = (const float*)d_in[5];
    const float* b2 = (const float*)d_in[6];
    float* out = (float*)d_out;

    cudaFuncSetAttribute(fused_kernel,
                         cudaFuncAttributeMaxDynamicSharedMemorySize, SMEM_SZ);

    prep_kernel<<<128, 256>>>(Wp, W1, W2);
    fused_kernel<<<512, 512, SMEM_SZ>>>(X, bp, b1, b2, out);
    subtract_kernel<<<dim3(16, 32), 256>>>(out);
}

// round 10
// speedup vs baseline: 1.0943x; 1.0943x over previous
#include <cuda_runtime.h>
#include <cuda_fp16.h>
#include <cstdint>

// ============================================================================
// X[16,4096,256] -> proj(256->128)+bp -> relu(W1+b1) -> W2+b2 = Y
// out[b,n,:] = sum_m Y[b,m,:] - Y[b,n,:]
// mma.sync.m16n8k16 fp16/f32. 512 CTAs x 256 thr (8 warps):
// warp w -> rows (w>>1)*32..+32, n-half (w&1)*64..+64  (R5 tiling).
// Weights streamed in 16KB chunks (double-buffered cp.async).
// X fp16 in SMEM (stride 528); H1 -> SM_H (272); H2 -> SM_X region (272):
// ping-pong like R5, so NO extra mid-loop syncs. A-frags via ldmatrix.x4.
// Column sums fused into the final epilogue -> g_part[tile][128].
// ============================================================================

__device__ __align__(16) uint32_t g_wpack[8 * 4096];  // 8 chunks x 16KB fp16 packed
__device__ float g_part[512 * 128];

// ---------------- helpers ----------------
__device__ __forceinline__ uint32_t smem_u32(const void* p) {
    uint32_t a;
    asm("{ .reg .u64 t; cvta.to.shared.u64 t, %1; cvt.u32.u64 %0, t; }" : "=r"(a) : "l"(p));
    return a;
}
__device__ __forceinline__ void lds64f(uint32_t a, float& x, float& y) {
    asm volatile("ld.shared.v2.f32 {%0,%1}, [%2];" : "=f"(x), "=f"(y) : "r"(a));
}
__device__ __forceinline__ void lds128u(uint32_t a, uint32_t& x, uint32_t& y, uint32_t& z, uint32_t& w) {
    asm volatile("ld.shared.v4.b32 {%0,%1,%2,%3}, [%4];" : "=r"(x), "=r"(y), "=r"(z), "=r"(w) : "r"(a));
}
__device__ __forceinline__ void sts32u(uint32_t a, uint32_t v) {
    asm volatile("st.shared.b32 [%0], %1;" :: "r"(a), "r"(v));
}
__device__ __forceinline__ void sts128u(uint32_t a, uint32_t x, uint32_t y, uint32_t z, uint32_t w) {
    asm volatile("st.shared.v4.b32 [%0], {%1,%2,%3,%4};" :: "r"(a), "r"(x), "r"(y), "r"(z), "r"(w));
}
__device__ __forceinline__ uint32_t packh2(float lo, float hi) {
    uint32_t u;
    asm("cvt.rn.f16x2.f32 %0, %1, %2;" : "=r"(u) : "f"(hi), "f"(lo));
    return u;
}
__device__ __forceinline__ void ldmA4(uint32_t a, uint32_t* r) {
    asm volatile("ldmatrix.sync.aligned.m8n8.x4.shared.b16 {%0,%1,%2,%3}, [%4];"
        : "=r"(r[0]), "=r"(r[1]), "=r"(r[2]), "=r"(r[3]) : "r"(a));
}
__device__ __forceinline__ void mma16(float* d,
                                      uint32_t a0, uint32_t a1, uint32_t a2, uint32_t a3,
                                      uint32_t b0, uint32_t b1) {
    asm volatile(
        "mma.sync.aligned.m16n8k16.row.col.f32.f16.f16.f32 "
        "{%0,%1,%2,%3}, {%4,%5,%6,%7}, {%8,%9}, {%0,%1,%2,%3};"
        : "+f"(d[0]), "+f"(d[1]), "+f"(d[2]), "+f"(d[3])
        : "r"(a0), "r"(a1), "r"(a2), "r"(a3), "r"(b0), "r"(b1));
}
#define CP16(dst, src)  asm volatile("cp.async.cg.shared.global [%0], [%1], 16;" :: "r"(dst), "l"(src))
#define CP_COMMIT()     asm volatile("cp.async.commit_group;" ::: "memory")
#define CP_WAIT(n)      asm volatile("cp.async.wait_group %0;" :: "n"(n) : "memory")

// ============================================================================
// prep: pack weights (fp16) into lane-ordered quad layout (proven R4-R9).
// chunk c (0..7) = 16KB K-slice of 64 rows x 128 cols (0-3:Wp, 4-5:W1, 6-7:W2).
// uint32 idx within chunk: ((ks*8+bp)*32 + lane)*4 + q, where
//   k_local = ks*16 + (q&1)*8 + (lane&3)*2 ; n = bp*16 + (q>>1)*8 + (lane>>2)
// ============================================================================
__global__ void prep_kernel(const float* __restrict__ Wp,
                            const float* __restrict__ W1,
                            const float* __restrict__ W2) {
    int i = blockIdx.x * 256 + threadIdx.x;          // 32768 total
    int chunk = i >> 12;
    int within = i & 4095;
    int q = within & 3, ln = (within >> 2) & 31, bpks = within >> 7;
    int bpi = bpks & 7, ks = bpks >> 3;
    int kl = ks * 16 + (q & 1) * 8 + (ln & 3) * 2;
    int n = bpi * 16 + (q >> 1) * 8 + (ln >> 2);
    const float* W;
    int krow;
    if (chunk < 4)      { W = Wp; krow = chunk * 64 + kl; }
    else if (chunk < 6) { W = W1; krow = (chunk - 4) * 64 + kl; }
    else                { W = W2; krow = (chunk - 6) * 64 + kl; }
    float w0 = W[(size_t)krow * 128 + n];
    float w1 = W[(size_t)(krow + 1) * 128 + n];
    g_wpack[i] = packh2(w0, w1);
}

// ============================================================================
// fused kernel — ~136KB SMEM, 256 threads (8 warps), occ 1, no reg cap.
// ============================================================================
#define SM_X    0                     // 128*528 = 67584 (X fp16 / later H2 @272)
#define SM_H    67584                 // 128*272 = 34816 (H1 fp16)
#define SM_W0   102400                // 16KB
#define SM_W1B  118784                // 16KB
#define SM_BIAS 135168                // bp[128], b1[128], b2[128] (f32)
#define SM_RED  136704                // 4*128 floats
#define SMEM_SZ 138752

// one 16KB chunk = 4 k-steps of 16; warp covers m=32 (2 ldmatrix.x4 per ks).
__device__ __forceinline__ void gemm_chunk(uint32_t a_lane, uint32_t astr16, uint32_t a_off,
                                           uint32_t wb, int nh, int l, float acc[2][8][4]) {
    #pragma unroll
    for (int ks = 0; ks < 4; ++ks) {
        uint32_t A0[4], A1[4];
        uint32_t aa = a_lane + a_off + (uint32_t)ks * 32;
        ldmA4(aa, A0);
        ldmA4(aa + astr16, A1);
        uint32_t bb = wb + (uint32_t)ks * 4096 + (uint32_t)(nh * 4) * 512 + (uint32_t)l * 16;
        #pragma unroll
        for (int bpi = 0; bpi < 4; ++bpi) {
            uint32_t q0, q1, q2, q3;
            lds128u(bb + (uint32_t)bpi * 512, q0, q1, q2, q3);
            mma16(acc[0][2 * bpi],     A0[0], A0[1], A0[2], A0[3], q0, q1);
            mma16(acc[1][2 * bpi],     A1[0], A1[1], A1[2], A1[3], q0, q1);
            mma16(acc[0][2 * bpi + 1], A0[0], A0[1], A0[2], A0[3], q2, q3);
            mma16(acc[1][2 * bpi + 1], A1[0], A1[1], A1[2], A1[3], q2, q3);
        }
    }
}

__global__ void __launch_bounds__(256, 1) fused_kernel(
    const float* __restrict__ X,
    const float* __restrict__ bp,
    const float* __restrict__ b1,
    const float* __restrict__ b2,
    float* __restrict__ out)
{
    extern __shared__ char smem[];
    const uint32_t sb = smem_u32(smem);
    const int tid = threadIdx.x;
    const int l = tid & 31;
    const int w = tid >> 5;
    const int wrow = (w >> 1) * 32;        // row group (32 rows per warp)
    const int nh = w & 1;                  // n-half
    const int t = blockIdx.x;

    // prefetch weight chunks 0,1 (two cp.async groups)
    {
        const uint4* ws = (const uint4*)g_wpack;
        for (int i = tid; i < 1024; i += 256) CP16(sb + SM_W0 + i * 16, ws + i);
        CP_COMMIT();
        for (int i = tid; i < 1024; i += 256) CP16(sb + SM_W1B + i * 16, ws + 1024 + i);
        CP_COMMIT();
    }
    if (tid < 128) {
        ((float*)(smem + SM_BIAS))[tid]       = bp[tid];
        ((float*)(smem + SM_BIAS))[128 + tid] = b1[tid];
        ((float*)(smem + SM_BIAS))[256 + tid] = b2[tid];
    }

    // X tile -> fp16 smem (row = tid>>1, half-row seg = tid&1), stride 528
    {
        const float4* xp = (const float4*)(X + ((size_t)t * 128 + (tid >> 1)) * 256 + (tid & 1) * 128);
        uint32_t sa = sb + SM_X + (uint32_t)(tid >> 1) * 528 + (uint32_t)(tid & 1) * 256;
        #pragma unroll
        for (int j = 0; j < 16; ++j) {
            float4 v0 = xp[2 * j], v1 = xp[2 * j + 1];
            sts128u(sa + (uint32_t)j * 16,
                    packh2(v0.x, v0.y), packh2(v0.z, v0.w),
                    packh2(v1.x, v1.y), packh2(v1.z, v1.w));
        }
    }
    __syncthreads();   // X visible to all warps

    float acc[2][8][4];
    #pragma unroll
    for (int m = 0; m < 2; ++m)
        #pragma unroll
        for (int nb = 0; nb < 8; ++nb)
            #pragma unroll
            for (int k = 0; k < 4; ++k) acc[m][nb][k] = 0.f;

    const uint32_t lm_row = (uint32_t)(l & 15);
    const uint32_t lm_hi  = (uint32_t)(l >> 4) * 16;
    const uint32_t aX  = sb + SM_X + ((uint32_t)wrow + lm_row) * 528 + lm_hi;  // X, stride 528
    const uint32_t aH1 = sb + SM_H + ((uint32_t)wrow + lm_row) * 272 + lm_hi;  // H1, stride 272
    const uint32_t aH2 = sb + SM_X + ((uint32_t)wrow + lm_row) * 272 + lm_hi;  // H2 (X region), 272

    for (int ch = 0; ch < 8; ++ch) {
        if (ch < 7) { CP_WAIT(1); } else { CP_WAIT(0); }
        __syncthreads();   // chunk ch ready; prev-chunk weight reads done

        const uint32_t wb = sb + ((ch & 1) ? SM_W1B : SM_W0);
        if (ch < 4)      gemm_chunk(aX,  16 * 528, (uint32_t)ch * 128,       wb, nh, l, acc);
        else if (ch < 6) gemm_chunk(aH1, 16 * 272, (uint32_t)(ch - 4) * 128, wb, nh, l, acc);
        else             gemm_chunk(aH2, 16 * 272, (uint32_t)(ch - 6) * 128, wb, nh, l, acc);

        if (ch == 3 || ch == 5) {
            // epi1 (ch3): H1 = acc+bp -> SM_H ; epi2 (ch5): H2 = relu(acc+b1) -> SM_X
            // (targets are regions whose readers finished >=1 barrier ago: no extra sync)
            const uint32_t dst = (ch == 3) ? (sb + SM_H) : (sb + SM_X);
            const uint32_t bo  = sb + SM_BIAS + (ch == 3 ? 0 : 512) + (uint32_t)nh * 256;
            const bool dorelu = (ch == 5);
            #pragma unroll
            for (int nb = 0; nb < 8; ++nb) {
                float bx, by;
                lds64f(bo + (uint32_t)(nb * 8 + (l & 3) * 2) * 4, bx, by);
                #pragma unroll
                for (int mb = 0; mb < 2; ++mb) {
                    float v0 = acc[mb][nb][0] + bx, v1 = acc[mb][nb][1] + by;
                    float v2 = acc[mb][nb][2] + bx, v3 = acc[mb][nb][3] + by;
                    if (dorelu) {
                        v0 = fmaxf(v0, 0.f); v1 = fmaxf(v1, 0.f);
                        v2 = fmaxf(v2, 0.f); v3 = fmaxf(v3, 0.f);
                    }
                    uint32_t sa = dst + (uint32_t)(wrow + mb * 16 + (l >> 2)) * 272
                                      + (uint32_t)(nh * 64 + nb * 8 + (l & 3) * 2) * 2;
                    sts32u(sa, packh2(v0, v1));
                    sts32u(sa + 8 * 272, packh2(v2, v3));
                    acc[mb][nb][0] = 0.f; acc[mb][nb][1] = 0.f;
                    acc[mb][nb][2] = 0.f; acc[mb][nb][3] = 0.f;
                }
            }
        } else if (ch == 7) {
            // final epilogue: Y -> gmem, fused per-tile column sums
            const size_t rb = (size_t)t * 128 + wrow + (l >> 2);
            float cs[8][2];
            #pragma unroll
            for (int nb = 0; nb < 8; ++nb) { cs[nb][0] = 0.f; cs[nb][1] = 0.f; }
            #pragma unroll
            for (int nb = 0; nb < 8; ++nb) {
                float bx, by;
                lds64f(sb + SM_BIAS + 1024 + (uint32_t)(nh * 64 + nb * 8 + (l & 3) * 2) * 4, bx, by);
                #pragma unroll
                for (int mb = 0; mb < 2; ++mb) {
                    float v0 = acc[mb][nb][0] + bx, v1 = acc[mb][nb][1] + by;
                    float v2 = acc[mb][nb][2] + bx, v3 = acc[mb][nb][3] + by;
                    size_t r0 = (rb + mb * 16) * 128 + nh * 64 + nb * 8 + (l & 3) * 2;
                    *(float2*)(out + r0)           = make_float2(v0, v1);
                    *(float2*)(out + r0 + 8 * 128) = make_float2(v2, v3);
                    cs[nb][0] += v0 + v2;
                    cs[nb][1] += v1 + v3;
                }
            }
            #pragma unroll
            for (int nb = 0; nb < 8; ++nb) {
                #pragma unroll
                for (int j = 0; j < 2; ++j) {
                    float s = cs[nb][j];
                    s += __shfl_down_sync(0xFFFFFFFFu, s, 16);
                    s += __shfl_down_sync(0xFFFFFFFFu, s, 8);
                    s += __shfl_down_sync(0xFFFFFFFFu, s, 4);
                    if (l < 4)
                        ((float*)(smem + SM_RED))[(w >> 1) * 128 + nh * 64 + nb * 8 + l * 2 + j] = s;
                }
            }
        }

        __syncthreads();   // weight-buffer reuse + H visibility for next chunk

        if (ch + 2 < 8) {  // prefetch weight chunk ch+2 into buffer (ch&1)
            const uint4* ws = (const uint4*)(g_wpack + (ch + 2) * 4096);
            uint32_t bdst = sb + ((ch & 1) ? SM_W1B : SM_W0);
            for (int i = tid; i < 1024; i += 256) CP16(bdst + i * 16, ws + i);
            CP_COMMIT();
        }
    }

    // fold 4 row-groups -> g_part[t][128]
    if (tid < 128) {
        const float* R = (const float*)(smem + SM_RED);
        g_part[(size_t)t * 128 + tid] = R[tid] + R[128 + tid] + R[256 + tid] + R[384 + tid];
    }
}

// ---------------- out = S - Y (in place, float4) ----------------
__global__ void subtract_kernel(float* __restrict__ out) {
    __shared__ float4 S4[32];
    int b = blockIdx.x, nc = blockIdx.y, tid = threadIdx.x;
    if (tid < 128) {
        float s = 0.f;
        const float* gp = g_part + (size_t)b * 32 * 128 + tid;
        #pragma unroll
        for (int c = 0; c < 32; ++c) s += gp[c * 128];
        ((float*)S4)[tid] = s;
    }
    __syncthreads();
    float4* p = (float4*)(out + ((size_t)b * 4096 + (size_t)nc * 128) * 128);
    for (int i = tid; i < 4096; i += 256) {
        float4 s = S4[i & 31];
        float4 v = p[i];
        p[i] = make_float4(s.x - v.x, s.y - v.y, s.z - v.z, s.w - v.w);
    }
}

// ---------------- launch ----------------
extern "C" void kernel_launch(void* const* d_in, const int* in_sizes, int n_in,
                              void* d_out, int out_size) {
    const float* X  = (const float*)d_in[0];
    const float* Wp = (const float*)d_in[1];
    const float* bp = (const float*)d_in[2];
    const float* W1 = (const float*)d_in[3];
    const float* b1 = (const float*)d_in[4];
    const float* W2 = (const float*)d_in[5];
    const float* b2 = (const float*)d_in[6];
    float* out = (float*)d_out;

    cudaFuncSetAttribute(fused_kernel,
                         cudaFuncAttributeMaxDynamicSharedMemorySize, SMEM_SZ);

    prep_kernel<<<128, 256>>>(Wp, W1, W2);
    fused_kernel<<<512, 256, SMEM_SZ>>>(X, bp, b1, b2, out);
    subtract_kernel<<<dim3(16, 32), 256>>>(out);
}